// round 1
// baseline (speedup 1.0000x reference)
#include <cuda_runtime.h>

// S4D diagonal SSM kernel:  out[h,l] = 2*Re( sum_n cmod[h,n] * z[h,n]^l )
//   z = exp(dtA), dtA = w*dt, cmod = C*(z-1)/w
// Factorization: l = 32*k + j  (k in [0,64), j in [0,32))
//   out[h,32k+j] = sum_n ( CBre[n,k]*Are[n,j] - CBim[n,k]*Aim[n,j] )
//   CB[n,k] = cmod_n * (z^32)^k,  A[n,j] = z^j

#define HDIM 1024
#define NDIM 64
#define LLEN 2048

#define CB_STRIDE 68   // 64 + 4 pad: 16B-aligned rows for LDS.128, de-conflicts setup STS
#define A_STRIDE  34   // 32 + 2 pad: 8B-aligned rows for LDS.64

#define SMEM_FLOATS (2*64*CB_STRIDE + 2*64*A_STRIDE)   // 13056 floats = 52224 bytes

struct c2 { float re, im; };
__device__ __forceinline__ c2 cmul(c2 a, c2 b) {
    return { fmaf(a.re, b.re, -a.im*b.im), fmaf(a.re, b.im, a.im*b.re) };
}

__global__ __launch_bounds__(256) void ssk_diag_kernel(
    const float* __restrict__ log_dt,
    const float* __restrict__ log_w_real,
    const float* __restrict__ w_imag,
    const float* __restrict__ C_re,
    const float* __restrict__ C_im,
    float* __restrict__ out)
{
    extern __shared__ float sm[];
    float* sBre = sm;                       // [64][CB_STRIDE]
    float* sBim = sBre + 64*CB_STRIDE;      // [64][CB_STRIDE]  (stores -Im)
    float* sAre = sBim + 64*CB_STRIDE;      // [64][A_STRIDE]
    float* sAim = sAre + 64*A_STRIDE;       // [64][A_STRIDE]

    const int h   = blockIdx.x;
    const int tid = threadIdx.x;

    // ---------------- Phase 1: per-head tables (256 threads = 64 n x 4 segments) --------
    {
        const int n  = tid & 63;
        const int kg = tid >> 6;            // segment 0..3

        const float dtv = expf(log_dt[h]);
        const float wre = -expf(log_w_real[h*NDIM + n]);
        const float wim = w_imag[h*NDIM + n];
        const float are = wre * dtv;        // dtA.re  (negative, small)
        const float aim = wim * dtv;        // dtA.im

        const float er = expf(are);
        float s, c; sincosf(aim, &s, &c);
        const c2 z = { er*c, er*s };

        // cmod = C * (z - 1) / w ; fold output factor 2 in here
        const float nre = z.re - 1.0f, nim = z.im;
        const float inv = 1.0f / (wre*wre + wim*wim);
        const float tre = (nre*wre + nim*wim) * inv;
        const float tim = (nim*wre - nre*wim) * inv;
        const float cr = C_re[h*NDIM + n], ci = C_im[h*NDIM + n];
        const c2 cm = { 2.0f*(cr*tre - ci*tim), 2.0f*(cr*tim + ci*tre) };

        // power ladder by squaring
        const c2 z2   = cmul(z,   z);
        const c2 z4   = cmul(z2,  z2);
        const c2 z8   = cmul(z4,  z4);
        const c2 z16  = cmul(z8,  z8);
        const c2 z32  = cmul(z16, z16);
        const c2 z64  = cmul(z32, z32);
        const c2 z128 = cmul(z64, z64);
        const c2 z256 = cmul(z128,z128);
        const c2 z512 = cmul(z256,z256);

        // A[n][j] = z^j for j = 8*kg .. 8*kg+7
        c2 a = {1.0f, 0.0f};
        if (kg & 1) a = z8;
        if (kg & 2) a = cmul(a, z16);
        #pragma unroll
        for (int jj = 0; jj < 8; jj++) {
            sAre[n*A_STRIDE + 8*kg + jj] = a.re;
            sAim[n*A_STRIDE + 8*kg + jj] = a.im;
            a = cmul(a, z);
        }

        // CB[n][k] = cmod * z32^k for k = 16*kg .. 16*kg+15 ; start = cmod * z512^kg
        c2 b = cm;
        if (kg & 1) b = cmul(b, z512);
        if (kg & 2) { const c2 z1024 = cmul(z512, z512); b = cmul(b, z1024); }
        #pragma unroll
        for (int kk = 0; kk < 16; kk++) {
            sBre[n*CB_STRIDE + 16*kg + kk] =  b.re;
            sBim[n*CB_STRIDE + 16*kg + kk] = -b.im;   // pre-negate: contraction is pure FMA
            b = cmul(b, z32);
        }
    }
    __syncthreads();

    // ---------------- Phase 2: contraction. Thread = 4 k x 2 j = 8 outputs --------------
    const int kq = tid >> 4;    // 0..15  -> k base = 4*kq
    const int jp = tid & 15;    // 0..15  -> j base = 2*jp

    const float* pBre = sBre + 4*kq;
    const float* pBim = sBim + 4*kq;
    const float* pAre = sAre + 2*jp;
    const float* pAim = sAim + 2*jp;

    float2 acc0 = {0.f,0.f}, acc1 = {0.f,0.f}, acc2 = {0.f,0.f}, acc3 = {0.f,0.f};

    #pragma unroll 8
    for (int n = 0; n < NDIM; n++) {
        const float4 br = *reinterpret_cast<const float4*>(pBre + n*CB_STRIDE);
        const float4 bi = *reinterpret_cast<const float4*>(pBim + n*CB_STRIDE);
        const float2 ar = *reinterpret_cast<const float2*>(pAre + n*A_STRIDE);
        const float2 ai = *reinterpret_cast<const float2*>(pAim + n*A_STRIDE);

        acc0.x = fmaf(br.x, ar.x, fmaf(bi.x, ai.x, acc0.x));
        acc0.y = fmaf(br.x, ar.y, fmaf(bi.x, ai.y, acc0.y));
        acc1.x = fmaf(br.y, ar.x, fmaf(bi.y, ai.x, acc1.x));
        acc1.y = fmaf(br.y, ar.y, fmaf(bi.y, ai.y, acc1.y));
        acc2.x = fmaf(br.z, ar.x, fmaf(bi.z, ai.x, acc2.x));
        acc2.y = fmaf(br.z, ar.y, fmaf(bi.z, ai.y, acc2.y));
        acc3.x = fmaf(br.w, ar.x, fmaf(bi.w, ai.x, acc3.x));
        acc3.y = fmaf(br.w, ar.y, fmaf(bi.w, ai.y, acc3.y));
    }

    // l = 32*(4*kq + kk) + 2*jp + jj  -> per-warp: two fully-coalesced 128B segments
    float* po = out + h*LLEN + kq*128 + jp*2;
    *reinterpret_cast<float2*>(po +  0) = acc0;
    *reinterpret_cast<float2*>(po + 32) = acc1;
    *reinterpret_cast<float2*>(po + 64) = acc2;
    *reinterpret_cast<float2*>(po + 96) = acc3;
}

extern "C" void kernel_launch(void* const* d_in, const int* in_sizes, int n_in,
                              void* d_out, int out_size)
{
    const float* log_dt     = (const float*)d_in[0];
    const float* log_w_real = (const float*)d_in[1];
    const float* w_imag     = (const float*)d_in[2];
    const float* C_re       = (const float*)d_in[3];
    const float* C_im       = (const float*)d_in[4];
    // d_in[5] is L (constant 2048), baked into LLEN
    float* out = (float*)d_out;

    const int smem_bytes = SMEM_FLOATS * (int)sizeof(float);   // 52224 > 48KB -> opt-in
    cudaFuncSetAttribute(ssk_diag_kernel,
                         cudaFuncAttributeMaxDynamicSharedMemorySize, smem_bytes);

    ssk_diag_kernel<<<HDIM, 256, smem_bytes>>>(log_dt, log_w_real, w_imag,
                                               C_re, C_im, out);
}